// round 8
// baseline (speedup 1.0000x reference)
#include <cuda_runtime.h>
#include <stdint.h>

#define OF 28672
#define IF 8192

__device__ float g_xs[256 * 40];   // per group: 34 pre-scaled x'' + 4 biases + 2 pad
__device__ float g_sumx;
__device__ float g_part[4 * OF];

__device__ const signed char c_xoff[34] = {
    0,1,2,3,4,5,6,7,8,9,10,
    10,11,12,13,14,15,16,17,18,19,20,21,
    21,22,23,24,25,26,27,28,29,30,31};
__device__ const signed char c_e[34] = {
    -16,-19,-14,-17,-20,-15,-18,-13,-16,-19,-14,
    -14,-17,-20,-15,-18,-13,-16,-19,-14,-17,-20,-15,
    -15,-18,-13,-16,-19,-14,-17,-20,-15,-18,-13};

// Prep: block 0 reduces sum(x); block 1 builds x'' table + per-group magic biases.
__global__ void prep_kernel(const float* __restrict__ x) {
    int t = threadIdx.x;
    if (blockIdx.x == 0) {
        __shared__ float red[256];
        float s = 0.f;
        for (int i = t; i < IF; i += 256) s += x[i];
        red[t] = s;
        __syncthreads();
        #pragma unroll
        for (int off = 128; off > 0; off >>= 1) {
            if (t < off) red[t] += red[t + off];
            __syncthreads();
        }
        if (t == 0) g_sumx = red[0];
    } else {
        int g = t;  // one group per thread, 256 groups
        float xr[32];
        #pragma unroll
        for (int i = 0; i < 32; i++) xr[i] = x[g * 32 + i];
        double b[4] = {0.0, 0.0, 0.0, 0.0};
        #pragma unroll
        for (int j = 0; j < 34; j++) {
            float v = ldexpf(xr[c_xoff[j]], c_e[j]);   // exact power-of-2 scale
            g_xs[g * 40 + j] = v;
            b[j & 3] += (double)v;
        }
        #pragma unroll
        for (int a = 0; a < 4; a++)
            g_xs[g * 40 + 34 + a] = (float)(b[a] * 8388608.0);  // 2^23 * sum
        g_xs[g * 40 + 38] = 0.f;
        g_xs[g * 40 + 39] = 0.f;
    }
}

// GEMV: grid (896, 4). CTA = 32 cols x 8 K-slices, K-quarter blockIdx.y.
// Per 3-bit code: 1 LOP3 (mask|magic) + 1 FFMA. No I2F anywhere.
__global__ void __launch_bounds__(256, 4) gemv3_kernel(const uint32_t* __restrict__ qw)
{
    __shared__ float smx[64 * 40];
    __shared__ float part[256];
    const int t = threadIdx.x;
    const int q = blockIdx.y;

    // stage this quarter's x'' table (10 KB)
    {
        const float4* src = (const float4*)g_xs + q * 640;
        float4* dst = (float4*)smx;
        #pragma unroll
        for (int i = t; i < 640; i += 256) dst[i] = src[i];
    }
    __syncthreads();

    const int lane = t & 31;
    const int sl   = t >> 5;
    const int col  = blockIdx.x * 32 + lane;
    const uint32_t* p = qw + (size_t)(3 * (q * 64 + sl * 8)) * OF + col;
    const float* xs = smx + sl * 8 * 40;

    float acc[4] = {0.f, 0.f, 0.f, 0.f};

    #pragma unroll 2
    for (int g = 0; g < 8; g++) {
        uint32_t w0 = p[0];
        uint32_t w1 = p[OF];
        uint32_t w2 = p[2 * OF];
        p += 3 * OF;

        float xv[40];
        #pragma unroll
        for (int i2 = 0; i2 < 10; i2++)
            ((float4*)xv)[i2] = ((const float4*)xs)[i2];
        xs += 40;

        uint32_t v;
        #define F(J, MASK) acc[(J) & 3] = fmaf( \
            __uint_as_float((v & (MASK)) | 0x4B000000u), xv[J], acc[(J) & 3])
        v = w0 << 16; F(0, 7u << 16); F(1, 7u << 19);
        v = w0 << 8;  F(2, 7u << 14); F(3, 7u << 17); F(4, 7u << 20);
        v = w0;       F(5, 7u << 15); F(6, 7u << 18);
        v = w0 >> 8;  F(7, 7u << 13); F(8, 7u << 16); F(9, 7u << 19);
        v = w0 >> 16; F(10, 3u << 14);
        v = w1 << 16; F(11, 1u << 16); F(12, 7u << 17); F(13, 7u << 20);
        v = w1 << 8;  F(14, 7u << 15); F(15, 7u << 18);
        v = w1;       F(16, 7u << 13); F(17, 7u << 16); F(18, 7u << 19);
        v = w1 >> 8;  F(19, 7u << 14); F(20, 7u << 17); F(21, 7u << 20);
        v = w1 >> 16; F(22, 1u << 15);
        v = w2 << 16; F(23, 3u << 16); F(24, 7u << 18);
        v = w2 << 8;  F(25, 7u << 13); F(26, 7u << 16); F(27, 7u << 19);
        v = w2;       F(28, 7u << 14); F(29, 7u << 17); F(30, 7u << 20);
        v = w2 >> 8;  F(31, 7u << 15); F(32, 7u << 18);
        v = w2 >> 16; F(33, 7u << 13);
        #undef F

        acc[0] -= xv[34];
        acc[1] -= xv[35];
        acc[2] -= xv[36];
        acc[3] -= xv[37];
    }

    part[t] = (acc[0] + acc[1]) + (acc[2] + acc[3]);
    __syncthreads();

    if (t < 32) {
        float dot = 0.f;
        #pragma unroll
        for (int k = 0; k < 8; k++) dot += part[t + 32 * k];
        g_part[q * OF + blockIdx.x * 32 + t] = dot;
    }
}

// Combine the 4 K-quarter partials + affine terms.
__global__ void combine_kernel(const float* __restrict__ scales,
                               const float* __restrict__ zeros,
                               const float* __restrict__ bias,
                               float* __restrict__ out)
{
    int i = blockIdx.x * 256 + threadIdx.x;
    if (i < OF) {
        float d = (g_part[i] + g_part[OF + i]) +
                  (g_part[2 * OF + i] + g_part[3 * OF + i]);
        out[i] = fmaf(scales[i], d, fmaf(-zeros[i], g_sumx, bias[i]));
    }
}

extern "C" void kernel_launch(void* const* d_in, const int* in_sizes, int n_in,
                              void* d_out, int out_size) {
    const float*    x      = (const float*)d_in[0];
    const uint32_t* qw     = (const uint32_t*)d_in[1];
    const float*    scales = (const float*)d_in[2];
    const float*    zeros  = (const float*)d_in[3];
    const float*    bias   = (const float*)d_in[4];
    float*          out    = (float*)d_out;

    prep_kernel<<<2, 256>>>(x);
    gemv3_kernel<<<dim3(OF / 32, 4), 256>>>(qw);
    combine_kernel<<<(OF + 255) / 256, 256>>>(scales, zeros, bias, out);
}

// round 9
// speedup vs baseline: 1.2296x; 1.2296x over previous
#include <cuda_runtime.h>
#include <stdint.h>

typedef unsigned long long ull;

#define OF 28672
#define IF 8192

// table: 256 groups x 40 ull (34 duplicated x'' pairs + 4 duplicated negbias pairs + 2 pad)
__device__ __align__(16) float g_xs[256 * 80];
__device__ float g_sumred[32];
__device__ float g_sumx;
__device__ float g_part[4 * OF];

__device__ const signed char c_xoff[34] = {
    0,1,2,3,4,5,6,7,8,9,10,
    10,11,12,13,14,15,16,17,18,19,20,21,
    21,22,23,24,25,26,27,28,29,30,31};
__device__ const signed char c_e[34] = {
    -10,-13,-16,-19,-12,-15,-18,-10,-13,-16,-19,
    -8,-11,-14,-17,-20,-13,-16,-19,-11,-14,-17,-20,
    -9,-12,-15,-18,-11,-14,-17,-20,-12,-15,-18};

__device__ __forceinline__ float pw2(int e) {
    return __int_as_float((127 + e) << 23);   // exact power of two
}

// prep1: 32 blocks x 256 -> partial sums of x
__global__ void prep1_kernel(const float* __restrict__ x) {
    __shared__ float red[256];
    int t = threadIdx.x;
    red[t] = x[blockIdx.x * 256 + t];
    __syncthreads();
    #pragma unroll
    for (int off = 128; off > 0; off >>= 1) {
        if (t < off) red[t] += red[t + off];
        __syncthreads();
    }
    if (t == 0) g_sumred[blockIdx.x] = red[0];
}

// prep2: builds duplicated x'' table + per-group neg biases + final sumx
__global__ void prep2_kernel(const float* __restrict__ x) {
    int e = blockIdx.x * 256 + threadIdx.x;
    if (e < 256 * 34) {
        int g = e / 34, j = e % 34;
        float v = x[g * 32 + c_xoff[j]] * pw2(c_e[j]);
        g_xs[g * 80 + 2 * j]     = v;
        g_xs[g * 80 + 2 * j + 1] = v;
    } else if (e < 256 * 34 + 256 * 4) {
        int i = e - 256 * 34;
        int g = i >> 2, a = i & 3;
        double s = 0.0;
        for (int j = a; j < 34; j += 4)
            s += (double)(x[g * 32 + c_xoff[j]] * pw2(c_e[j]));
        float nb = (float)(s * -8388608.0);   // -2^23 * sum
        g_xs[g * 80 + 68 + 2 * a]     = nb;
        g_xs[g * 80 + 68 + 2 * a + 1] = nb;
    } else if (e == 256 * 34 + 256 * 4) {
        float s = 0.f;
        #pragma unroll
        for (int k = 0; k < 32; k++) s += g_sumred[k];
        g_sumx = s;
    }
}

#define MAGIC64 0x4B0000004B000000ull
#define M64(m)  ((ull)(m) * 0x100000001ull)

#define FMA2(ACC, A, B) asm("fma.rn.f32x2 %0, %1, %2, %0;" : "+l"(ACC) : "l"(A), "l"(B))
#define ADD2(ACC, B)    asm("add.rn.f32x2 %0, %0, %1;"     : "+l"(ACC) : "l"(B))

// GEMV: grid (448, 4), 256 thr. Thread = 2 adjacent columns x 8 K-slices.
// All bit ops done in 64-bit (two columns per register pair); one FFMA2 per field.
__global__ void __launch_bounds__(256) gemv3_kernel(const uint32_t* __restrict__ qw)
{
    __shared__ __align__(16) ull smx[2560];   // 64 groups x 40 ull
    __shared__ ull part[256];
    const int t = threadIdx.x;
    const int q = blockIdx.y;

    {
        const ulonglong2* src = (const ulonglong2*)g_xs + q * 1280;
        ulonglong2* dst = (ulonglong2*)smx;
        #pragma unroll
        for (int i = 0; i < 5; i++) dst[t + 256 * i] = src[t + 256 * i];
    }
    __syncthreads();

    const int lane = t & 31;
    const int sl   = t >> 5;
    const ull* p = (const ull*)(qw + (size_t)(3 * (q * 64 + sl * 8)) * OF
                                   + blockIdx.x * 64) + lane;
    const ull* xs = smx + (sl * 8) * 40;

    ull acc[4] = {0ull, 0ull, 0ull, 0ull};

    #pragma unroll 2
    for (int g = 0; g < 8; g++) {
        ull w0 = __ldcs(p);
        ull w1 = __ldcs(p + OF / 2);
        ull w2 = __ldcs(p + OF);
        p += 3 * (OF / 2);

        ulonglong2 xv2[19];
        const ull* xv = (const ull*)xv2;

        // chunk 1: xv[0..17]
        #pragma unroll
        for (int i = 0; i < 9; i++) xv2[i] = ((const ulonglong2*)xs)[i];

        ull v;
        #define F(J, M) { ull mm = (v & M64(M)) | MAGIC64; FMA2(acc[(J) & 3], mm, xv[J]); }
        v = w0 << 10; F(0, 7u << 10); F(1, 7u << 13); F(2, 7u << 16); F(3, 7u << 19);
        v = w0;       F(4, 7u << 12); F(5, 7u << 15); F(6, 7u << 18);
        v = w0 >> 11; F(7, 7u << 10); F(8, 7u << 13); F(9, 7u << 16); F(10, 3u << 19);
        v = w1 << 10; F(11, 1u << 10); F(12, 7u << 11); F(13, 7u << 14); F(14, 7u << 17); F(15, 7u << 20);
        v = w1;       F(16, 7u << 13); F(17, 7u << 16);

        // chunk 2: xv[18..37]
        #pragma unroll
        for (int i = 9; i < 19; i++) xv2[i] = ((const ulonglong2*)xs)[i];

        /* v still = w1 */ F(18, 7u << 19);
        v = w1 >> 11; F(19, 7u << 11); F(20, 7u << 14); F(21, 7u << 17); F(22, 1u << 20);
        v = w2 << 10; F(23, 3u << 10); F(24, 7u << 12); F(25, 7u << 15); F(26, 7u << 18);
        v = w2;       F(27, 7u << 11); F(28, 7u << 14); F(29, 7u << 17); F(30, 7u << 20);
        v = w2 >> 11; F(31, 7u << 12); F(32, 7u << 15); F(33, 7u << 18);
        #undef F

        ADD2(acc[0], xv[34]);
        ADD2(acc[1], xv[35]);
        ADD2(acc[2], xv[36]);
        ADD2(acc[3], xv[37]);

        xs += 40;
    }

    ADD2(acc[0], acc[1]);
    ADD2(acc[2], acc[3]);
    ADD2(acc[0], acc[2]);
    part[t] = acc[0];
    __syncthreads();

    if (t < 64) {
        const float* pf = (const float*)part;
        float dot = 0.f;
        #pragma unroll
        for (int s = 0; s < 8; s++)
            dot += pf[(s * 32 + (t >> 1)) * 2 + (t & 1)];
        g_part[q * OF + blockIdx.x * 64 + t] = dot;
    }
}

// Combine the 4 K-quarter partials + affine terms.
__global__ void combine_kernel(const float* __restrict__ scales,
                               const float* __restrict__ zeros,
                               const float* __restrict__ bias,
                               float* __restrict__ out)
{
    int i = blockIdx.x * 256 + threadIdx.x;
    if (i < OF) {
        float d = (g_part[i] + g_part[OF + i]) +
                  (g_part[2 * OF + i] + g_part[3 * OF + i]);
        out[i] = fmaf(scales[i], d, fmaf(-zeros[i], g_sumx, bias[i]));
    }
}

extern "C" void kernel_launch(void* const* d_in, const int* in_sizes, int n_in,
                              void* d_out, int out_size) {
    const float*    x      = (const float*)d_in[0];
    const uint32_t* qw     = (const uint32_t*)d_in[1];
    const float*    scales = (const float*)d_in[2];
    const float*    zeros  = (const float*)d_in[3];
    const float*    bias   = (const float*)d_in[4];
    float*          out    = (float*)d_out;

    prep1_kernel<<<32, 256>>>(x);
    prep2_kernel<<<(256 * 34 + 256 * 4 + 1 + 255) / 256, 256>>>(x);
    gemv3_kernel<<<dim3(OF / 64, 4), 256>>>(qw);
    combine_kernel<<<(OF + 255) / 256, 256>>>(scales, zeros, bias, out);
}